// round 2
// baseline (speedup 1.0000x reference)
#include <cuda_runtime.h>
#include <math.h>

#define Bz 64
#define Tz 256
#define Fz 512
#define Hz 1024
#define Oz 512

// Persistent device state (no allocations allowed)
__device__ float g_h[2][Bz * Hz];        // ping-pong hidden state
__device__ float g_logits[Bz * Fz];      // logits from previous step
__device__ float g_currin[Bz * Fz];      // masked input for current step
__device__ int   g_nsel;                 // integer selection count (exact)

__device__ __forceinline__ float sigmf(float v) {
    return 1.0f / (1.0f + expf(-v));
}

// ---------------------------------------------------------------------------
// init: zero h[0] and the selection counter
// ---------------------------------------------------------------------------
__global__ void init_kernel() {
    int i = blockIdx.x * blockDim.x + threadIdx.x;
    if (i < Bz * Hz) g_h[0][i] = 0.0f;
    if (i == 0) g_nsel = 0;
}

// ---------------------------------------------------------------------------
// mask: sig = sigmoid(prev logits); w = sig > u; curr_in = w * x_t
//       writes sel_weights[t] and accumulates integer count (t > 0)
// grid 128 x 256  (covers B*F = 32768)
// ---------------------------------------------------------------------------
__global__ __launch_bounds__(256) void mask_kernel(
    int t,
    const float* __restrict__ x,      // [B, T, F]
    const float* __restrict__ u,      // [T, B, F]
    float* __restrict__ selw)         // [T, B, F] region of d_out
{
    int i = blockIdx.x * 256 + threadIdx.x;   // i = b*512 + f
    int b = i >> 9;
    int f = i & 511;

    float xv = x[(size_t)(b * Tz + t) * Fz + f];
    float w, ci;
    if (t == 0) {
        w = 1.0f;
        ci = xv;
    } else {
        float sg = sigmf(g_logits[i]);
        w = (sg > u[(size_t)t * (Bz * Fz) + i]) ? 1.0f : 0.0f;
        ci = w * xv;
    }
    g_currin[i] = ci;
    selw[(size_t)t * (Bz * Fz) + i] = w;

    if (t > 0) {
        int cnt = (int)w;
        #pragma unroll
        for (int o = 16; o; o >>= 1)
            cnt += __shfl_down_sync(0xffffffffu, cnt, o);
        __shared__ int sred[8];
        int wi = threadIdx.x >> 5;
        if ((threadIdx.x & 31) == 0) sred[wi] = cnt;
        __syncthreads();
        if (threadIdx.x == 0) {
            int tot = 0;
            #pragma unroll
            for (int k = 0; k < 8; k++) tot += sred[k];
            atomicAdd(&g_nsel, tot);
        }
    }
}

// ---------------------------------------------------------------------------
// gates: gi = curr_in @ W_ih^T, gh = h @ W_hh^T, GRU update -> h_new
// 128 blocks (8 hidden units each) x 256 threads (2-way K split).
// Thread tile: 2 batches x 2 units x {r,z,in,hn}.
// ---------------------------------------------------------------------------
__global__ __launch_bounds__(256) void gates_kernel(
    int t,
    const float* __restrict__ Wih, const float* __restrict__ bih,
    const float* __restrict__ Whh, const float* __restrict__ bhh)
{
    __shared__ float Ct[2][64][33];
    __shared__ float Wt[2][3][8][33];
    __shared__ float Red[128 * 17];

    const float* __restrict__ hin = g_h[t & 1];
    float* __restrict__ hout = g_h[(t + 1) & 1];

    const int tid = threadIdx.x;
    const int kz = tid >> 7;       // K-split half: 0 or 1
    const int t2 = tid & 127;
    const int bq = t2 & 31;        // batches bq and bq+32
    const int jg = t2 >> 5;        // 0..3 -> units jg*2, jg*2+1
    const int j0 = blockIdx.x * 8;

    float accr[2][2]  = {{0.f,0.f},{0.f,0.f}};
    float accz[2][2]  = {{0.f,0.f},{0.f,0.f}};
    float accin[2][2] = {{0.f,0.f},{0.f,0.f}};
    float acchn[2][2] = {{0.f,0.f},{0.f,0.f}};

    // ---- Loop 1: input contribution (K = 512), half range [kz*256, kz*256+256)
    for (int kb = kz * 256; kb < kz * 256 + 256; kb += 32) {
        __syncthreads();
        #pragma unroll
        for (int i = 0; i < 4; i++) {
            int idx = t2 + i * 128;            // < 512
            int row = idx >> 3, q = idx & 7;
            float4 v = *(const float4*)(g_currin + row * 512 + kb + q * 4);
            Ct[kz][row][q*4+0] = v.x; Ct[kz][row][q*4+1] = v.y;
            Ct[kz][row][q*4+2] = v.z; Ct[kz][row][q*4+3] = v.w;
        }
        #pragma unroll
        for (int i = 0; i < 2; i++) {
            int idx = t2 + i * 128;
            if (idx < 192) {
                int g = idx >> 6, rem = idx & 63, ju = rem >> 3, q = rem & 7;
                float4 v = *(const float4*)(Wih + (size_t)(g * Hz + j0 + ju) * 512 + kb + q * 4);
                Wt[kz][g][ju][q*4+0] = v.x; Wt[kz][g][ju][q*4+1] = v.y;
                Wt[kz][g][ju][q*4+2] = v.z; Wt[kz][g][ju][q*4+3] = v.w;
            }
        }
        __syncthreads();
        #pragma unroll
        for (int kk = 0; kk < 32; kk++) {
            float c0 = Ct[kz][bq][kk], c1 = Ct[kz][bq + 32][kk];
            #pragma unroll
            for (int jt = 0; jt < 2; jt++) {
                int ju = jg * 2 + jt;
                float wr = Wt[kz][0][ju][kk];
                float wz = Wt[kz][1][ju][kk];
                float wn = Wt[kz][2][ju][kk];
                accr[0][jt]  += c0 * wr; accr[1][jt]  += c1 * wr;
                accz[0][jt]  += c0 * wz; accz[1][jt]  += c1 * wz;
                accin[0][jt] += c0 * wn; accin[1][jt] += c1 * wn;
            }
        }
    }

    // ---- Loop 2: hidden contribution (K = 1024), half range [kz*512, kz*512+512)
    for (int kb = kz * 512; kb < kz * 512 + 512; kb += 32) {
        __syncthreads();
        #pragma unroll
        for (int i = 0; i < 4; i++) {
            int idx = t2 + i * 128;
            int row = idx >> 3, q = idx & 7;
            float4 v = *(const float4*)(hin + (size_t)row * 1024 + kb + q * 4);
            Ct[kz][row][q*4+0] = v.x; Ct[kz][row][q*4+1] = v.y;
            Ct[kz][row][q*4+2] = v.z; Ct[kz][row][q*4+3] = v.w;
        }
        #pragma unroll
        for (int i = 0; i < 2; i++) {
            int idx = t2 + i * 128;
            if (idx < 192) {
                int g = idx >> 6, rem = idx & 63, ju = rem >> 3, q = rem & 7;
                float4 v = *(const float4*)(Whh + (size_t)(g * Hz + j0 + ju) * 1024 + kb + q * 4);
                Wt[kz][g][ju][q*4+0] = v.x; Wt[kz][g][ju][q*4+1] = v.y;
                Wt[kz][g][ju][q*4+2] = v.z; Wt[kz][g][ju][q*4+3] = v.w;
            }
        }
        __syncthreads();
        #pragma unroll
        for (int kk = 0; kk < 32; kk++) {
            float c0 = Ct[kz][bq][kk], c1 = Ct[kz][bq + 32][kk];
            #pragma unroll
            for (int jt = 0; jt < 2; jt++) {
                int ju = jg * 2 + jt;
                float wr = Wt[kz][0][ju][kk];
                float wz = Wt[kz][1][ju][kk];
                float wn = Wt[kz][2][ju][kk];
                accr[0][jt]  += c0 * wr; accr[1][jt]  += c1 * wr;
                accz[0][jt]  += c0 * wz; accz[1][jt]  += c1 * wz;
                acchn[0][jt] += c0 * wn; acchn[1][jt] += c1 * wn;
            }
        }
    }

    // ---- combine K halves
    __syncthreads();
    if (kz == 1) {
        float* p = Red + t2 * 17;
        p[0]  = accr[0][0];  p[1]  = accr[0][1];  p[2]  = accr[1][0];  p[3]  = accr[1][1];
        p[4]  = accz[0][0];  p[5]  = accz[0][1];  p[6]  = accz[1][0];  p[7]  = accz[1][1];
        p[8]  = accin[0][0]; p[9]  = accin[0][1]; p[10] = accin[1][0]; p[11] = accin[1][1];
        p[12] = acchn[0][0]; p[13] = acchn[0][1]; p[14] = acchn[1][0]; p[15] = acchn[1][1];
    }
    __syncthreads();
    if (kz == 0) {
        const float* p = Red + t2 * 17;
        accr[0][0]  += p[0];  accr[0][1]  += p[1];  accr[1][0]  += p[2];  accr[1][1]  += p[3];
        accz[0][0]  += p[4];  accz[0][1]  += p[5];  accz[1][0]  += p[6];  accz[1][1]  += p[7];
        accin[0][0] += p[8];  accin[0][1] += p[9];  accin[1][0] += p[10]; accin[1][1] += p[11];
        acchn[0][0] += p[12]; acchn[0][1] += p[13]; acchn[1][0] += p[14]; acchn[1][1] += p[15];

        #pragma unroll
        for (int bt = 0; bt < 2; bt++) {
            int b = bq + bt * 32;
            #pragma unroll
            for (int jt = 0; jt < 2; jt++) {
                int j = j0 + jg * 2 + jt;
                float r  = sigmf(accr[bt][jt] + bih[j] + bhh[j]);
                float z  = sigmf(accz[bt][jt] + bih[Hz + j] + bhh[Hz + j]);
                float in = accin[bt][jt] + bih[2 * Hz + j];
                float hn = acchn[bt][jt] + bhh[2 * Hz + j];
                float n  = tanhf(in + r * hn);
                float hp = hin[(size_t)b * Hz + j];
                hout[(size_t)b * Hz + j] = (1.0f - z) * n + z * hp;
            }
        }
    }
}

// ---------------------------------------------------------------------------
// houts: out[t] = h @ W_out^T + b_out ; logits = h @ W_sel^T + b_sel
// 1024 virtual columns (512 out + 512 sel). 128 blocks x 128 threads.
// ---------------------------------------------------------------------------
__global__ __launch_bounds__(128) void houts_kernel(
    int t,
    const float* __restrict__ Wout, const float* __restrict__ bout,
    const float* __restrict__ Wsel, const float* __restrict__ bsel,
    float* __restrict__ outbase)     // d_out (outputs region)
{
    __shared__ float Ht[64][33];
    __shared__ float Wt[8][33];

    const float* __restrict__ h = g_h[(t + 1) & 1];

    const int tid = threadIdx.x;
    const int bq = tid & 31;
    const int cg = tid >> 5;       // 0..3
    const int c0 = blockIdx.x * 8;

    float acc[2][2] = {{0.f,0.f},{0.f,0.f}};

    for (int kb = 0; kb < 1024; kb += 32) {
        __syncthreads();
        #pragma unroll
        for (int i = 0; i < 4; i++) {
            int idx = tid + i * 128;          // < 512
            int row = idx >> 3, q = idx & 7;
            float4 v = *(const float4*)(h + (size_t)row * 1024 + kb + q * 4);
            Ht[row][q*4+0] = v.x; Ht[row][q*4+1] = v.y;
            Ht[row][q*4+2] = v.z; Ht[row][q*4+3] = v.w;
        }
        if (tid < 64) {
            int rw = tid >> 3, q = tid & 7;
            int c = c0 + rw;
            const float* W = (c < 512) ? (Wout + (size_t)c * 1024)
                                       : (Wsel + (size_t)(c - 512) * 1024);
            float4 v = *(const float4*)(W + kb + q * 4);
            Wt[rw][q*4+0] = v.x; Wt[rw][q*4+1] = v.y;
            Wt[rw][q*4+2] = v.z; Wt[rw][q*4+3] = v.w;
        }
        __syncthreads();
        #pragma unroll
        for (int kk = 0; kk < 32; kk++) {
            float h0 = Ht[bq][kk], h1 = Ht[bq + 32][kk];
            #pragma unroll
            for (int ct = 0; ct < 2; ct++) {
                float w = Wt[cg * 2 + ct][kk];
                acc[0][ct] += h0 * w;
                acc[1][ct] += h1 * w;
            }
        }
    }

    #pragma unroll
    for (int bt = 0; bt < 2; bt++) {
        int b = bq + bt * 32;
        #pragma unroll
        for (int ct = 0; ct < 2; ct++) {
            int c = c0 + cg * 2 + ct;
            if (c < 512) {
                outbase[(size_t)t * Bz * Oz + (size_t)b * Oz + c] = acc[bt][ct] + bout[c];
            } else {
                g_logits[b * 512 + (c - 512)] = acc[bt][ct] + bsel[c - 512];
            }
        }
    }
}

// ---------------------------------------------------------------------------
// finalize: write num_selections (integer count, exact in fp32)
// ---------------------------------------------------------------------------
__global__ void finalize_kernel(float* __restrict__ out) {
    if (threadIdx.x == 0 && blockIdx.x == 0) {
        out[(size_t)Tz * Bz * Oz] = (float)g_nsel;
    }
}

// ---------------------------------------------------------------------------
extern "C" void kernel_launch(void* const* d_in, const int* in_sizes, int n_in,
                              void* d_out, int out_size) {
    const float* x    = (const float*)d_in[0];
    const float* u    = (const float*)d_in[1];
    const float* Wih  = (const float*)d_in[2];
    const float* bih  = (const float*)d_in[3];
    const float* Whh  = (const float*)d_in[4];
    const float* bhh  = (const float*)d_in[5];
    const float* Wout = (const float*)d_in[6];
    const float* bout = (const float*)d_in[7];
    const float* Wsel = (const float*)d_in[8];
    const float* bsel = (const float*)d_in[9];

    float* out  = (float*)d_out;
    float* selw = out + (size_t)Tz * Bz * Oz + 1;

    init_kernel<<<256, 256>>>();
    for (int t = 0; t < Tz; t++) {
        mask_kernel<<<128, 256>>>(t, x, u, selw);
        gates_kernel<<<128, 256>>>(t, Wih, bih, Whh, bhh);
        houts_kernel<<<128, 128>>>(t, Wout, bout, Wsel, bsel, out);
    }
    finalize_kernel<<<1, 32>>>(out);
}

// round 3
// speedup vs baseline: 1.5707x; 1.5707x over previous
#include <cuda_runtime.h>
#include <math.h>

#define Bz 64
#define Tz 256
#define Fz 512
#define Hz 1024
#define Oz 512

// Persistent device state (transposed layouts: [feature][batch])
__device__ __align__(16) float g_hT[2][Hz * Bz];   // hidden state ping-pong, [j][b]
__device__ __align__(16) float g_cinT[Fz * Bz];    // masked input, [f][b]
__device__ int g_nsel;

__device__ __forceinline__ float sigmf(float v) { return 1.0f / (1.0f + expf(-v)); }

// ---------------------------------------------------------------------------
// init: h[0] = 0, curr_in = x[:,0,:] (transposed), selw[0] = 1, nsel = 0
// ---------------------------------------------------------------------------
__global__ void init_kernel(const float* __restrict__ x, float* __restrict__ selw) {
    int i = blockIdx.x * blockDim.x + threadIdx.x;
    if (i < Hz * Bz) g_hT[0][i] = 0.0f;
    if (i < Fz * Bz) {
        int b = i >> 9;          // Fz = 512
        int f = i & 511;
        float v = x[(size_t)b * Tz * Fz + f];    // x[b][0][f]
        g_cinT[f * Bz + b] = v;
        selw[(size_t)b * Fz + f] = 1.0f;
    }
    if (i == 0) g_nsel = 0;
}

// ---------------------------------------------------------------------------
// gates GEMM inner machinery (shared by F-loop and H-loop)
// Block: 128 threads = ut(8 units) x bt(8) x kz(2 K-split halves)
//   tid = ut*16 + bt*2 + kz ; thread tile = 8 batches x 1 unit x 3 gates
// SMEM: double-buffered, per-chunk KC=32 k-values per kz half.
// ---------------------------------------------------------------------------
template<int KHALF, int NC, int LDW>
__device__ __forceinline__ void gemm_gates(
    const float* __restrict__ actT,    // [k][b] transposed activations
    const float* __restrict__ Wsrc,    // [3*Hz][LDW]
    int j0, int tid, int kz, int ut, int b0,
    float (&As)[2][2][32][68], float (&Ws)[2][2][872],
    float* accr, float* accz, float* accn)
{
    float4 pa[8];
    float4 pw[3];

    auto ldA = [&](int c) {
        #pragma unroll
        for (int i = 0; i < 8; i++) {
            int lin = tid + i * 128;
            int kzs = lin >> 9;
            int rem = lin & 511;
            int k   = rem >> 4;
            int b4  = (rem & 15) << 2;
            pa[i] = *(const float4*)(actT + (size_t)(kzs * KHALF + c * 32 + k) * Bz + b4);
        }
        #pragma unroll
        for (int i = 0; i < 3; i++) {
            int lin = tid + i * 128;                // 0..383
            int kzs = (lin >= 192) ? 1 : 0;
            int rem = lin - kzs * 192;
            int row = rem >> 3;                     // 0..23 (g*8+u)
            int q   = rem & 7;
            int g   = row >> 3;
            int uu  = row & 7;
            pw[i] = *(const float4*)(Wsrc + (size_t)(g * Hz + j0 + uu) * LDW
                                     + kzs * KHALF + c * 32 + q * 4);
        }
    };
    auto stA = [&](int p) {
        #pragma unroll
        for (int i = 0; i < 8; i++) {
            int lin = tid + i * 128;
            int kzs = lin >> 9;
            int rem = lin & 511;
            int k   = rem >> 4;
            int b4  = (rem & 15) << 2;
            *(float4*)&As[p][kzs][k][b4] = pa[i];
        }
        #pragma unroll
        for (int i = 0; i < 3; i++) {
            int lin = tid + i * 128;
            int kzs = (lin >= 192) ? 1 : 0;
            int rem = lin - kzs * 192;
            int row = rem >> 3;
            int q   = rem & 7;
            *(float4*)&Ws[p][kzs][row * 36 + q * 4] = pw[i];
        }
    };
    auto comp = [&](int p) {
        #pragma unroll 8
        for (int kk = 0; kk < 32; kk++) {
            float4 a0 = *(const float4*)&As[p][kz][kk][b0];
            float4 a1 = *(const float4*)&As[p][kz][kk][b0 + 4];
            float a[8] = {a0.x, a0.y, a0.z, a0.w, a1.x, a1.y, a1.z, a1.w};
            float wr = Ws[p][kz][(0 * 8 + ut) * 36 + kk];
            float wz = Ws[p][kz][(1 * 8 + ut) * 36 + kk];
            float wn = Ws[p][kz][(2 * 8 + ut) * 36 + kk];
            #pragma unroll
            for (int i = 0; i < 8; i++) {
                accr[i] += a[i] * wr;
                accz[i] += a[i] * wz;
                accn[i] += a[i] * wn;
            }
        }
    };

    ldA(0);
    stA(0);
    __syncthreads();
    for (int c = 0; c < NC; c++) {
        if (c + 1 < NC) ldA(c + 1);     // LDG into regs (latency hidden by comp)
        comp(c & 1);
        if (c + 1 < NC) stA((c + 1) & 1);
        __syncthreads();
    }
}

// ---------------------------------------------------------------------------
// gates: gi = curr_in @ W_ih^T, gh = h @ W_hh^T, GRU update -> hT[(t+1)&1]
// grid 128 (8 units each) x 128 threads
// ---------------------------------------------------------------------------
__global__ __launch_bounds__(128) void gates_kernel(
    int t,
    const float* __restrict__ Wih, const float* __restrict__ bih,
    const float* __restrict__ Whh, const float* __restrict__ bhh)
{
    __shared__ __align__(16) float As[2][2][32][68];
    __shared__ __align__(16) float Ws[2][2][872];

    const float* __restrict__ hinT = g_hT[t & 1];
    float* __restrict__ houtT = g_hT[(t + 1) & 1];

    const int tid = threadIdx.x;
    const int kz = tid & 1;
    const int bt = (tid >> 1) & 7;
    const int ut = tid >> 4;
    const int b0 = bt * 8;
    const int j0 = blockIdx.x * 8;

    float accr[8], accz[8], accni[8], accnh[8];
    #pragma unroll
    for (int i = 0; i < 8; i++) { accr[i] = 0.f; accz[i] = 0.f; accni[i] = 0.f; accnh[i] = 0.f; }

    // input contribution: K = 512 (256 per kz half, 8 chunks)
    gemm_gates<256, 8, 512>(g_cinT, Wih, j0, tid, kz, ut, b0, As, Ws, accr, accz, accni);
    // hidden contribution: K = 1024 (512 per kz half, 16 chunks)
    gemm_gates<512, 16, 1024>(hinT, Whh, j0, tid, kz, ut, b0, As, Ws, accr, accz, accnh);

    // combine K-split halves (kz is lane bit 0)
    #pragma unroll
    for (int i = 0; i < 8; i++) {
        accr[i]  += __shfl_xor_sync(0xffffffffu, accr[i],  1);
        accz[i]  += __shfl_xor_sync(0xffffffffu, accz[i],  1);
        accni[i] += __shfl_xor_sync(0xffffffffu, accni[i], 1);
        accnh[i] += __shfl_xor_sync(0xffffffffu, accnh[i], 1);
    }

    if (kz == 0) {
        int j = j0 + ut;
        float br  = bih[j] + bhh[j];
        float bz  = bih[Hz + j] + bhh[Hz + j];
        float bni = bih[2 * Hz + j];
        float bnh = bhh[2 * Hz + j];
        float res[8];
        #pragma unroll
        for (int i = 0; i < 8; i++) {
            float r = sigmf(accr[i] + br);
            float z = sigmf(accz[i] + bz);
            float n = tanhf(accni[i] + bni + r * (accnh[i] + bnh));
            float hp = hinT[j * Bz + b0 + i];
            res[i] = (1.0f - z) * n + z * hp;
        }
        *(float4*)&houtT[j * Bz + b0]     = make_float4(res[0], res[1], res[2], res[3]);
        *(float4*)&houtT[j * Bz + b0 + 4] = make_float4(res[4], res[5], res[6], res[7]);
    }
}

// ---------------------------------------------------------------------------
// houts: 1024 virtual cols (512 out + 512 sel) = h @ [W_out; W_sel]^T + bias.
// Sel-column blocks fuse next step's Bernoulli mask: write sel_weights[t+1],
// curr_in[t+1] (transposed) and the integer selection count.
// grid 128 (8 cols each) x 128 threads: ct(8) x bt(8) x kz(2), tile 8b x 1c.
// ---------------------------------------------------------------------------
__global__ __launch_bounds__(128) void houts_kernel(
    int t,
    const float* __restrict__ Wout, const float* __restrict__ bout,
    const float* __restrict__ Wsel, const float* __restrict__ bsel,
    const float* __restrict__ x, const float* __restrict__ u,
    float* __restrict__ out, float* __restrict__ selw)
{
    __shared__ __align__(16) float As[2][2][32][68];
    __shared__ __align__(16) float Ws[2][2][296];

    const float* __restrict__ hT = g_hT[(t + 1) & 1];

    const int tid = threadIdx.x;
    const int kz = tid & 1;
    const int bt = (tid >> 1) & 7;
    const int ct = tid >> 4;
    const int b0 = bt * 8;
    const int c0 = blockIdx.x * 8;

    // staging coordinates for W (one float4 per thread per chunk)
    const int skzs = tid >> 6;
    const int srem = tid & 63;
    const int srow = srem >> 3;
    const int sq   = srem & 7;
    const int scc  = c0 + srow;
    const float* __restrict__ wrow = (scc < Oz) ? (Wout + (size_t)scc * Hz)
                                                : (Wsel + (size_t)(scc - Oz) * Hz);

    float acc[8];
    #pragma unroll
    for (int i = 0; i < 8; i++) acc[i] = 0.f;

    float4 pa[8];
    float4 pw;

    auto ldA = [&](int c) {
        #pragma unroll
        for (int i = 0; i < 8; i++) {
            int lin = tid + i * 128;
            int kzs = lin >> 9;
            int rem = lin & 511;
            int k   = rem >> 4;
            int b4  = (rem & 15) << 2;
            pa[i] = *(const float4*)(hT + (size_t)(kzs * 512 + c * 32 + k) * Bz + b4);
        }
        pw = *(const float4*)(wrow + skzs * 512 + c * 32 + sq * 4);
    };
    auto stA = [&](int p) {
        #pragma unroll
        for (int i = 0; i < 8; i++) {
            int lin = tid + i * 128;
            int kzs = lin >> 9;
            int rem = lin & 511;
            int k   = rem >> 4;
            int b4  = (rem & 15) << 2;
            *(float4*)&As[p][kzs][k][b4] = pa[i];
        }
        *(float4*)&Ws[p][skzs][srow * 36 + sq * 4] = pw;
    };
    auto comp = [&](int p) {
        #pragma unroll 8
        for (int kk = 0; kk < 32; kk++) {
            float4 a0 = *(const float4*)&As[p][kz][kk][b0];
            float4 a1 = *(const float4*)&As[p][kz][kk][b0 + 4];
            float a[8] = {a0.x, a0.y, a0.z, a0.w, a1.x, a1.y, a1.z, a1.w};
            float w = Ws[p][kz][ct * 36 + kk];
            #pragma unroll
            for (int i = 0; i < 8; i++) acc[i] += a[i] * w;
        }
    };

    ldA(0);
    stA(0);
    __syncthreads();
    for (int c = 0; c < 16; c++) {
        if (c + 1 < 16) ldA(c + 1);
        comp(c & 1);
        if (c + 1 < 16) stA((c + 1) & 1);
        __syncthreads();
    }

    #pragma unroll
    for (int i = 0; i < 8; i++)
        acc[i] += __shfl_xor_sync(0xffffffffu, acc[i], 1);

    int cnt = 0;
    if (kz == 0) {
        int c = c0 + ct;
        if (c < Oz) {
            float bb = bout[c];
            #pragma unroll
            for (int i = 0; i < 8; i++)
                out[(size_t)t * Bz * Oz + (size_t)(b0 + i) * Oz + c] = acc[i] + bb;
        } else if (t < Tz - 1) {
            int f = c - Oz;
            float bb = bsel[f];
            float cin[8];
            #pragma unroll
            for (int i = 0; i < 8; i++) {
                float lg = acc[i] + bb;
                float sg = sigmf(lg);
                float uu = u[((size_t)(t + 1) * Bz + b0 + i) * Fz + f];
                float w  = (sg > uu) ? 1.0f : 0.0f;
                selw[((size_t)(t + 1) * Bz + b0 + i) * Fz + f] = w;
                cnt += (int)w;
                cin[i] = w * x[((size_t)(b0 + i) * Tz + t + 1) * Fz + f];
            }
            *(float4*)&g_cinT[f * Bz + b0]     = make_float4(cin[0], cin[1], cin[2], cin[3]);
            *(float4*)&g_cinT[f * Bz + b0 + 4] = make_float4(cin[4], cin[5], cin[6], cin[7]);
        }
    }
    #pragma unroll
    for (int o = 16; o; o >>= 1) cnt += __shfl_down_sync(0xffffffffu, cnt, o);
    if ((tid & 31) == 0 && cnt) atomicAdd(&g_nsel, cnt);
}

// ---------------------------------------------------------------------------
__global__ void finalize_kernel(float* __restrict__ out) {
    out[(size_t)Tz * Bz * Oz] = (float)g_nsel;
}

// ---------------------------------------------------------------------------
extern "C" void kernel_launch(void* const* d_in, const int* in_sizes, int n_in,
                              void* d_out, int out_size) {
    const float* x    = (const float*)d_in[0];
    const float* u    = (const float*)d_in[1];
    const float* Wih  = (const float*)d_in[2];
    const float* bih  = (const float*)d_in[3];
    const float* Whh  = (const float*)d_in[4];
    const float* bhh  = (const float*)d_in[5];
    const float* Wout = (const float*)d_in[6];
    const float* bout = (const float*)d_in[7];
    const float* Wsel = (const float*)d_in[8];
    const float* bsel = (const float*)d_in[9];

    float* out  = (float*)d_out;
    float* selw = out + (size_t)Tz * Bz * Oz + 1;

    init_kernel<<<(Hz * Bz + 255) / 256, 256>>>(x, selw);
    for (int t = 0; t < Tz; t++) {
        gates_kernel<<<128, 128>>>(t, Wih, bih, Whh, bhh);
        houts_kernel<<<128, 128>>>(t, Wout, bout, Wsel, bsel, x, u, out, selw);
    }
    finalize_kernel<<<1, 1>>>(out);
}

// round 4
// speedup vs baseline: 2.0390x; 1.2981x over previous
#include <cuda_runtime.h>
#include <math.h>

#define Bz 64
#define Tz 256
#define Fz 512
#define Hz 1024
#define Oz 512

// Persistent device state (transposed layouts: [feature][batch])
__device__ __align__(16) float g_hT[2][Hz * Bz];   // hidden state ping-pong, [j][b]
__device__ __align__(16) float g_cinT[Fz * Bz];    // masked input, [f][b]
__device__ int g_nsel;

__device__ __forceinline__ float sigmf(float v) { return 1.0f / (1.0f + expf(-v)); }

// ---------------------------------------------------------------------------
// init: h[0] = 0, curr_in = x[:,0,:] (transposed), selw[0] = 1, nsel = 0
// ---------------------------------------------------------------------------
__global__ void init_kernel(const float* __restrict__ x, float* __restrict__ selw) {
    int i = blockIdx.x * blockDim.x + threadIdx.x;
    if (i < Hz * Bz) g_hT[0][i] = 0.0f;
    if (i < Fz * Bz) {
        int b = i >> 9;
        int f = i & 511;
        float v = x[(size_t)b * Tz * Fz + f];    // x[b][0][f]
        g_cinT[f * Bz + b] = v;
        selw[(size_t)b * Fz + f] = 1.0f;
    }
    if (i == 0) g_nsel = 0;
}

// ---------------------------------------------------------------------------
// gates GEMM core. 256 threads: bt = tid&7 (lane bits 0-2, batches bt*4 and
// 32+bt*4), kz = (tid>>3)&3 (4-way K split), ut = tid>>5 (unit j0+ut).
// Per chunk: 64 k-values (16 per kz quarter), double-buffered SMEM with
// register prefetch. A reads are contiguous 128B per lane-octet (no bank
// conflicts); W reads broadcast within octets.
// ---------------------------------------------------------------------------
template<int KQ, int NC, int LDW>
__device__ __forceinline__ void gemm_gates(
    const float* __restrict__ actT,    // [k][b]
    const float* __restrict__ Wsrc,    // [3*Hz][LDW]
    int j0, int tid, int kz, int ut, int b0,
    float (&As)[2][4][16][64], float (&Ws)[2][4][480],
    float* accr, float* accz, float* accn)
{
    float4 pa[4];
    float4 pw[2];

    auto ldA = [&](int c) {
        #pragma unroll
        for (int i = 0; i < 4; i++) {
            int lin = tid + i * 256;            // 0..1023
            int q   = lin >> 8;
            int rem = lin & 255;
            int k   = rem >> 4;
            int b4  = (rem & 15) << 2;
            pa[i] = *(const float4*)(actT + (size_t)(q * KQ + c * 16 + k) * Bz + b4);
        }
        #pragma unroll
        for (int i = 0; i < 2; i++) {
            int lin = tid + i * 256;            // need 384 float4
            if (lin < 384) {
                int row = lin >> 4;             // 0..23  (g*8 + u)
                int kq4 = lin & 15;             // float4 index across 64 k
                int q   = kq4 >> 2;
                int qf  = kq4 & 3;
                int g   = row >> 3;
                int uu  = row & 7;
                pw[i] = *(const float4*)(Wsrc + (size_t)(g * Hz + j0 + uu) * LDW
                                         + q * KQ + c * 16 + qf * 4);
            }
        }
    };
    auto stA = [&](int p) {
        #pragma unroll
        for (int i = 0; i < 4; i++) {
            int lin = tid + i * 256;
            int q   = lin >> 8;
            int rem = lin & 255;
            int k   = rem >> 4;
            int b4  = (rem & 15) << 2;
            *(float4*)&As[p][q][k][b4] = pa[i];
        }
        #pragma unroll
        for (int i = 0; i < 2; i++) {
            int lin = tid + i * 256;
            if (lin < 384) {
                int row = lin >> 4;
                int kq4 = lin & 15;
                int q   = kq4 >> 2;
                int qf  = kq4 & 3;
                *(float4*)&Ws[p][q][row * 20 + qf * 4] = pw[i];
            }
        }
    };
    auto comp = [&](int p) {
        #pragma unroll
        for (int kk = 0; kk < 16; kk++) {
            float4 a0 = *(const float4*)&As[p][kz][kk][b0];
            float4 a1 = *(const float4*)&As[p][kz][kk][32 + b0];
            float a[8] = {a0.x, a0.y, a0.z, a0.w, a1.x, a1.y, a1.z, a1.w};
            float wr = Ws[p][kz][(0 * 8 + ut) * 20 + kk];
            float wz = Ws[p][kz][(1 * 8 + ut) * 20 + kk];
            float wn = Ws[p][kz][(2 * 8 + ut) * 20 + kk];
            #pragma unroll
            for (int i = 0; i < 8; i++) {
                accr[i] += a[i] * wr;
                accz[i] += a[i] * wz;
                accn[i] += a[i] * wn;
            }
        }
    };

    ldA(0);
    stA(0);
    __syncthreads();
    for (int c = 0; c < NC; c++) {
        if (c + 1 < NC) ldA(c + 1);
        comp(c & 1);
        if (c + 1 < NC) stA((c + 1) & 1);
        __syncthreads();
    }
}

// ---------------------------------------------------------------------------
// gates: gi = curr_in @ W_ih^T, gh = h @ W_hh^T, GRU update -> hT[(t+1)&1]
// grid 128 (8 units each) x 256 threads
// ---------------------------------------------------------------------------
__global__ __launch_bounds__(256) void gates_kernel(
    int t,
    const float* __restrict__ Wih, const float* __restrict__ bih,
    const float* __restrict__ Whh, const float* __restrict__ bhh)
{
    __shared__ __align__(16) float As[2][4][16][64];   // 32 KB
    __shared__ __align__(16) float Ws[2][4][480];      // 15 KB

    const float* __restrict__ hinT = g_hT[t & 1];
    float* __restrict__ houtT = g_hT[(t + 1) & 1];

    const int tid = threadIdx.x;
    const int bt = tid & 7;
    const int kz = (tid >> 3) & 3;
    const int ut = tid >> 5;
    const int b0 = bt * 4;
    const int j0 = blockIdx.x * 8;

    float accr[8], accz[8], accni[8], accnh[8];
    #pragma unroll
    for (int i = 0; i < 8; i++) { accr[i] = 0.f; accz[i] = 0.f; accni[i] = 0.f; accnh[i] = 0.f; }

    // input contribution: K = 512 (KQ = 128, 8 chunks of 64)
    gemm_gates<128, 8, 512>(g_cinT, Wih, j0, tid, kz, ut, b0, As, Ws, accr, accz, accni);
    // hidden contribution: K = 1024 (KQ = 256, 16 chunks of 64)
    gemm_gates<256, 16, 1024>(hinT, Whh, j0, tid, kz, ut, b0, As, Ws, accr, accz, accnh);

    // combine K-split quarters (kz = lane bits 3,4)
    #pragma unroll
    for (int i = 0; i < 8; i++) {
        accr[i]  += __shfl_xor_sync(0xffffffffu, accr[i],  8);
        accz[i]  += __shfl_xor_sync(0xffffffffu, accz[i],  8);
        accni[i] += __shfl_xor_sync(0xffffffffu, accni[i], 8);
        accnh[i] += __shfl_xor_sync(0xffffffffu, accnh[i], 8);
        accr[i]  += __shfl_xor_sync(0xffffffffu, accr[i],  16);
        accz[i]  += __shfl_xor_sync(0xffffffffu, accz[i],  16);
        accni[i] += __shfl_xor_sync(0xffffffffu, accni[i], 16);
        accnh[i] += __shfl_xor_sync(0xffffffffu, accnh[i], 16);
    }

    if (kz == 0) {
        int j = j0 + ut;
        float br  = bih[j] + bhh[j];
        float bz  = bih[Hz + j] + bhh[Hz + j];
        float bni = bih[2 * Hz + j];
        float bnh = bhh[2 * Hz + j];
        float4 hp0 = *(const float4*)(hinT + (size_t)j * Bz + b0);
        float4 hp1 = *(const float4*)(hinT + (size_t)j * Bz + 32 + b0);
        float hp[8] = {hp0.x, hp0.y, hp0.z, hp0.w, hp1.x, hp1.y, hp1.z, hp1.w};
        float res[8];
        #pragma unroll
        for (int i = 0; i < 8; i++) {
            float r = sigmf(accr[i] + br);
            float z = sigmf(accz[i] + bz);
            float n = tanhf(accni[i] + bni + r * (accnh[i] + bnh));
            res[i] = (1.0f - z) * n + z * hp[i];
        }
        *(float4*)&houtT[(size_t)j * Bz + b0]      = make_float4(res[0], res[1], res[2], res[3]);
        *(float4*)&houtT[(size_t)j * Bz + 32 + b0] = make_float4(res[4], res[5], res[6], res[7]);
    }
}

// ---------------------------------------------------------------------------
// houts: 1024 virtual cols (512 out + 512 sel) = h @ [W_out; W_sel]^T + bias.
// Sel-column warps fuse next step's Bernoulli mask.
// grid 128 (8 cols each) x 256 threads: bt(8) x kz(4) x ct(8).
// ---------------------------------------------------------------------------
__global__ __launch_bounds__(256) void houts_kernel(
    int t,
    const float* __restrict__ Wout, const float* __restrict__ bout,
    const float* __restrict__ Wsel, const float* __restrict__ bsel,
    const float* __restrict__ x, const float* __restrict__ u,
    float* __restrict__ out, float* __restrict__ selw)
{
    __shared__ __align__(16) float As[2][4][16][64];   // 32 KB
    __shared__ __align__(16) float Ws[2][4][160];      // 5 KB

    const float* __restrict__ hT = g_hT[(t + 1) & 1];

    const int tid = threadIdx.x;
    const int bt = tid & 7;
    const int kz = (tid >> 3) & 3;
    const int ct = tid >> 5;
    const int b0 = bt * 4;
    const int c0 = blockIdx.x * 8;

    // W staging: 8 rows x 64 k = 128 float4, tid < 128
    const int srow = tid >> 4;
    const int skq4 = tid & 15;
    const int sq   = skq4 >> 2;
    const int sqf  = skq4 & 3;
    const int scc  = c0 + srow;
    const float* __restrict__ wrow = (scc < Oz) ? (Wout + (size_t)scc * Hz)
                                                : (Wsel + (size_t)(scc - Oz) * Hz);

    float acc[8];
    #pragma unroll
    for (int i = 0; i < 8; i++) acc[i] = 0.f;

    float4 pa[4];
    float4 pw;

    auto ldA = [&](int c) {
        #pragma unroll
        for (int i = 0; i < 4; i++) {
            int lin = tid + i * 256;
            int q   = lin >> 8;
            int rem = lin & 255;
            int k   = rem >> 4;
            int b4  = (rem & 15) << 2;
            pa[i] = *(const float4*)(hT + (size_t)(q * 256 + c * 16 + k) * Bz + b4);
        }
        if (tid < 128)
            pw = *(const float4*)(wrow + sq * 256 + c * 16 + sqf * 4);
    };
    auto stA = [&](int p) {
        #pragma unroll
        for (int i = 0; i < 4; i++) {
            int lin = tid + i * 256;
            int q   = lin >> 8;
            int rem = lin & 255;
            int k   = rem >> 4;
            int b4  = (rem & 15) << 2;
            *(float4*)&As[p][q][k][b4] = pa[i];
        }
        if (tid < 128)
            *(float4*)&Ws[p][sq][srow * 20 + sqf * 4] = pw;
    };
    auto comp = [&](int p) {
        #pragma unroll
        for (int kk = 0; kk < 16; kk++) {
            float4 a0 = *(const float4*)&As[p][kz][kk][b0];
            float4 a1 = *(const float4*)&As[p][kz][kk][32 + b0];
            float a[8] = {a0.x, a0.y, a0.z, a0.w, a1.x, a1.y, a1.z, a1.w};
            float w = Ws[p][kz][ct * 20 + kk];
            #pragma unroll
            for (int i = 0; i < 8; i++) acc[i] += a[i] * w;
        }
    };

    ldA(0);
    stA(0);
    __syncthreads();
    for (int c = 0; c < 16; c++) {
        if (c + 1 < 16) ldA(c + 1);
        comp(c & 1);
        if (c + 1 < 16) stA((c + 1) & 1);
        __syncthreads();
    }

    #pragma unroll
    for (int i = 0; i < 8; i++) {
        acc[i] += __shfl_xor_sync(0xffffffffu, acc[i], 8);
        acc[i] += __shfl_xor_sync(0xffffffffu, acc[i], 16);
    }

    int cnt = 0;
    if (kz == 0) {
        int c = c0 + ct;
        if (c < Oz) {
            float bb = bout[c];
            #pragma unroll
            for (int i = 0; i < 8; i++) {
                int b = (i < 4) ? (b0 + i) : (32 + b0 + i - 4);
                out[(size_t)t * Bz * Oz + (size_t)b * Oz + c] = acc[i] + bb;
            }
        } else if (t < Tz - 1) {
            int f = c - Oz;
            float bb = bsel[f];
            float cin[8];
            #pragma unroll
            for (int i = 0; i < 8; i++) {
                int b = (i < 4) ? (b0 + i) : (32 + b0 + i - 4);
                float lg = acc[i] + bb;
                float sg = sigmf(lg);
                float uu = u[((size_t)(t + 1) * Bz + b) * Fz + f];
                float w  = (sg > uu) ? 1.0f : 0.0f;
                selw[((size_t)(t + 1) * Bz + b) * Fz + f] = w;
                cnt += (int)w;
                cin[i] = w * x[((size_t)b * Tz + t + 1) * Fz + f];
            }
            *(float4*)&g_cinT[f * Bz + b0]      = make_float4(cin[0], cin[1], cin[2], cin[3]);
            *(float4*)&g_cinT[f * Bz + 32 + b0] = make_float4(cin[4], cin[5], cin[6], cin[7]);
        }
    }
    #pragma unroll
    for (int o = 16; o; o >>= 1) cnt += __shfl_down_sync(0xffffffffu, cnt, o);
    if ((tid & 31) == 0 && cnt) atomicAdd(&g_nsel, cnt);
}

// ---------------------------------------------------------------------------
__global__ void finalize_kernel(float* __restrict__ out) {
    out[(size_t)Tz * Bz * Oz] = (float)g_nsel;
}

// ---------------------------------------------------------------------------
extern "C" void kernel_launch(void* const* d_in, const int* in_sizes, int n_in,
                              void* d_out, int out_size) {
    const float* x    = (const float*)d_in[0];
    const float* u    = (const float*)d_in[1];
    const float* Wih  = (const float*)d_in[2];
    const float* bih  = (const float*)d_in[3];
    const float* Whh  = (const float*)d_in[4];
    const float* bhh  = (const float*)d_in[5];
    const float* Wout = (const float*)d_in[6];
    const float* bout = (const float*)d_in[7];
    const float* Wsel = (const float*)d_in[8];
    const float* bsel = (const float*)d_in[9];

    float* out  = (float*)d_out;
    float* selw = out + (size_t)Tz * Bz * Oz + 1;

    init_kernel<<<(Hz * Bz + 255) / 256, 256>>>(x, selw);
    for (int t = 0; t < Tz; t++) {
        gates_kernel<<<128, 256>>>(t, Wih, bih, Whh, bhh);
        houts_kernel<<<128, 256>>>(t, Wout, bout, Wsel, bsel, x, u, out, selw);
    }
    finalize_kernel<<<1, 1>>>(out);
}